// round 1
// baseline (speedup 1.0000x reference)
#include <cuda_runtime.h>
#include <math.h>

#define NB 8
#define NC 3

// ---------------- scratch (device globals; no runtime allocation) ----------------
__device__ float g_x [NB*NC*256*256];   // sample conv output
__device__ float g_h0[NB*NC*512*512];   // ctx stage 0 out
__device__ float g_h1[NB*NC*256*256];   // ctx stage 1 out
__device__ float g_h2[NB*NC*128*128];   // ctx stage 2 out (pre-tanh feat_1)
__device__ float g_h3[NB*NC*64*64];     // ctx stage 3 out (pre-tanh feat_2)
__device__ float g_p1[NB*NC*128*128];
__device__ float g_p2[NB*NC*64*64];
__device__ float g_inv_sigma;
__device__ unsigned int g_counts[8];
__device__ unsigned int g_esti16;       // esti_size in units of 1/16 (exact integer)

// ---------------- init: zero accumulators + spectral norm of sample_w ----------------
__global__ void k_init(const float* __restrict__ w) {
    int t = threadIdx.x;
    if (t < 8) g_counts[t] = 0u;
    if (t == 0) {
        g_esti16 = 0u;
        // Gram matrix G = A A^T for A = sample_w reshaped (3, 48)
        double G[9];
        for (int i = 0; i < 3; i++)
            for (int j = 0; j < 3; j++) {
                double s = 0.0;
                for (int k = 0; k < 48; k++)
                    s += (double)w[i*48 + k] * (double)w[j*48 + k];
                G[i*3 + j] = s;
            }
        double v0 = 1.0, v1 = 1.0, v2 = 1.0;
        for (int it = 0; it < 256; it++) {
            double w0 = G[0]*v0 + G[1]*v1 + G[2]*v2;
            double w1 = G[3]*v0 + G[4]*v1 + G[5]*v2;
            double w2 = G[6]*v0 + G[7]*v1 + G[8]*v2;
            double n = sqrt(w0*w0 + w1*w1 + w2*w2);
            v0 = w0/n; v1 = w1/n; v2 = w2/n;
        }
        double lam = v0*(G[0]*v0 + G[1]*v1 + G[2]*v2)
                   + v1*(G[3]*v0 + G[4]*v1 + G[5]*v2)
                   + v2*(G[6]*v0 + G[7]*v1 + G[8]*v2);
        g_inv_sigma = (float)(1.0 / sqrt(lam));
    }
}

// ---------------- sample conv: 4x4, stride 4, pad 0; 1024 -> 256 ----------------
__global__ void k_sample(const float* __restrict__ x,
                         const float* __restrict__ w,
                         const float* __restrict__ bias) {
    __shared__ float sw[144];
    __shared__ float sb[3];
    __shared__ float sinv;
    for (int j = threadIdx.x; j < 144; j += 256) sw[j] = w[j];
    if (threadIdx.x < 3) sb[threadIdx.x] = bias[threadIdx.x];
    if (threadIdx.x == 0) sinv = g_inv_sigma;
    __syncthreads();

    int ox = threadIdx.x;      // 0..255
    int oy = blockIdx.x;       // 0..255
    int b  = blockIdx.y;       // 0..7
    float a0 = 0.f, a1 = 0.f, a2 = 0.f;
    #pragma unroll
    for (int ic = 0; ic < 3; ic++) {
        const float* base = x + (((b*3 + ic)*1024) + oy*4)*1024 + ox*4;
        #pragma unroll
        for (int ky = 0; ky < 4; ky++) {
            float4 v = *reinterpret_cast<const float4*>(base + ky*1024);
            const float* w0 = &sw[((0*3 + ic)*4 + ky)*4];
            const float* w1 = &sw[((1*3 + ic)*4 + ky)*4];
            const float* w2 = &sw[((2*3 + ic)*4 + ky)*4];
            a0 += w0[0]*v.x + w0[1]*v.y + w0[2]*v.z + w0[3]*v.w;
            a1 += w1[0]*v.x + w1[1]*v.y + w1[2]*v.z + w1[3]*v.w;
            a2 += w2[0]*v.x + w2[1]*v.y + w2[2]*v.z + w2[3]*v.w;
        }
    }
    g_x[((b*3 + 0)*256 + oy)*256 + ox] = a0*sinv + sb[0];
    g_x[((b*3 + 1)*256 + oy)*256 + ox] = a1*sinv + sb[1];
    g_x[((b*3 + 2)*256 + oy)*256 + ox] = a2*sinv + sb[2];
}

// ---------------- ctx conv stage: conv3x3(s2,p1) of relu(bn(in)) ----------------
template<int STAGE>
__global__ void k_ctx(const float* __restrict__ xin,
                      const float* __restrict__ w,
                      const float* __restrict__ bias,
                      const float* __restrict__ bng,
                      const float* __restrict__ bnb) {
    const float* in;
    float* out;
    int inH;
    if (STAGE == 0)      { in = xin;  out = g_h0; inH = 1024; }
    else if (STAGE == 1) { in = g_h0; out = g_h1; inH = 512; }
    else if (STAGE == 2) { in = g_h1; out = g_h2; inH = 256; }
    else                 { in = g_h2; out = g_h3; inH = 128; }
    const int inW = inH, outH = inH >> 1, outW = inW >> 1;

    __shared__ float sw[81];
    __shared__ float sb[3], sinv[3], sbb[3];
    for (int j = threadIdx.x; j < 81; j += blockDim.x) sw[j] = w[j];
    if (threadIdx.x < 3) {
        sb[threadIdx.x]  = bias[threadIdx.x];
        sinv[threadIdx.x] = bng[threadIdx.x] / sqrtf(1.001f);
        sbb[threadIdx.x] = bnb[threadIdx.x];
    }
    __syncthreads();

    int ox = threadIdx.x;
    if (ox >= outW) return;
    int oy = blockIdx.x;
    int b  = blockIdx.y;

    float a0 = sb[0], a1 = sb[1], a2 = sb[2];
    #pragma unroll
    for (int ic = 0; ic < 3; ic++) {
        const float* base = in + (size_t)(b*3 + ic)*inH*inW;
        float inv = sinv[ic], bb = sbb[ic];
        #pragma unroll
        for (int ky = 0; ky < 3; ky++) {
            int iy = 2*oy + ky - 1;
            if ((unsigned)iy >= (unsigned)inH) continue;
            #pragma unroll
            for (int kx = 0; kx < 3; kx++) {
                int ix = 2*ox + kx - 1;
                if ((unsigned)ix >= (unsigned)inW) continue;
                float v = base[iy*inW + ix];
                v = fmaxf(fmaf(inv, v, bb), 0.0f);     // relu(bn(.)) then zero-pad
                int wi = ic*9 + ky*3 + kx;
                a0 = fmaf(sw[wi],      v, a0);
                a1 = fmaf(sw[27 + wi], v, a1);
                a2 = fmaf(sw[54 + wi], v, a2);
            }
        }
    }
    out[((b*3 + 0)*outH + oy)*outW + ox] = a0;
    out[((b*3 + 1)*outH + oy)*outW + ox] = a1;
    out[((b*3 + 2)*outH + oy)*outW + ox] = a2;
}

// ---------------- pool conv: 2x2 stride 2 pad 0 ----------------
template<int STAGE>
__global__ void k_pool(const float* __restrict__ w,
                       const float* __restrict__ bias) {
    const float* in;
    float* out;
    int inH;
    if (STAGE == 0) { in = g_x;  out = g_p1; inH = 256; }
    else            { in = g_p1; out = g_p2; inH = 128; }
    const int inW = inH, outH = inH >> 1, outW = inW >> 1;

    __shared__ float sw[36];
    __shared__ float sb[3];
    for (int j = threadIdx.x; j < 36; j += blockDim.x) sw[j] = w[j];
    if (threadIdx.x < 3) sb[threadIdx.x] = bias[threadIdx.x];
    __syncthreads();

    int ox = threadIdx.x;
    if (ox >= outW) return;
    int oy = blockIdx.x;
    int b  = blockIdx.y;

    float a0 = sb[0], a1 = sb[1], a2 = sb[2];
    #pragma unroll
    for (int ic = 0; ic < 3; ic++) {
        const float* base = in + ((size_t)(b*3 + ic)*inH + 2*oy)*inW + 2*ox;
        float2 r0 = *reinterpret_cast<const float2*>(base);
        float2 r1 = *reinterpret_cast<const float2*>(base + inW);
        const float* w0 = &sw[(0*3 + ic)*4];
        const float* w1 = &sw[(1*3 + ic)*4];
        const float* w2 = &sw[(2*3 + ic)*4];
        a0 += w0[0]*r0.x + w0[1]*r0.y + w0[2]*r1.x + w0[3]*r1.y;
        a1 += w1[0]*r0.x + w1[1]*r0.y + w1[2]*r1.x + w1[3]*r1.y;
        a2 += w2[0]*r0.x + w2[1]*r0.y + w2[2]*r1.x + w2[3]*r1.y;
    }
    out[((b*3 + 0)*outH + oy)*outW + ox] = a0;
    out[((b*3 + 1)*outH + oy)*outW + ox] = a1;
    out[((b*3 + 2)*outH + oy)*outW + ox] = a2;
}

// ---------------- main fused pass: conditions + soft VQ + stats ----------------
__global__ void k_main(const float* __restrict__ thresh,
                       const float* __restrict__ centers,
                       float* __restrict__ out) {
    __shared__ float sc[8];
    __shared__ unsigned int shist[8];
    __shared__ unsigned int sesti;
    __shared__ float sth[2];
    if (threadIdx.x < 8) { sc[threadIdx.x] = centers[threadIdx.x]; shist[threadIdx.x] = 0u; }
    if (threadIdx.x < 2) sth[threadIdx.x] = thresh[threadIdx.x];
    if (threadIdx.x == 0) sesti = 0u;
    __syncthreads();

    int i = blockIdx.x*blockDim.x + threadIdx.x;
    unsigned int ev = 0u;
    if (i < NB*NC*256*256) {
        int xp = i & 255, y = (i >> 8) & 255, bc = i >> 16;
        float xv = g_x[i];
        int hi = bc*16384 + (y >> 1)*128 + (xp >> 1);  // half-res index
        int qi = bc*4096  + (y >> 2)*64  + (xp >> 2);  // quarter-res index
        float f1 = 0.5f*(tanhf(g_h2[hi]) + 1.0f);
        float f2 = 0.5f*(tanhf(g_h3[qi]) + 1.0f);
        bool c2 = f2 < sth[1];
        bool c1 = (!c2) && (f1 < sth[0]);
        bool c0 = !(c1 || c2);
        float xq = xv;
        if (c1) xq = g_p1[hi];
        if (c2) xq = g_p2[qi];

        float dd[8];
        float dmin = 3.4e38f;
        int imin = 0;
        #pragma unroll
        for (int k = 0; k < 8; k++) {
            float t = xq - sc[k];
            dd[k] = t*t;
            if (dd[k] < dmin) { dmin = dd[k]; imin = k; }
        }
        float s = 0.f, sn = 0.f;
        #pragma unroll
        for (int k = 0; k < 8; k++) {
            float e = __expf(dmin - dd[k]);
            s += e;
            sn = fmaf(e, sc[k], sn);
        }
        out[i] = sn / s;

        ev = c0 ? 16u : (c1 ? 4u : 1u);
        // cond_0 => xq == xv, so imin is argmin over x's distances too
        if (c0) atomicAdd(&shist[imin], 1u);
    }
    unsigned int wsum = __reduce_add_sync(0xffffffffu, ev);
    if ((threadIdx.x & 31) == 0) atomicAdd(&sesti, wsum);
    __syncthreads();
    if (threadIdx.x < 8 && shist[threadIdx.x]) atomicAdd(&g_counts[threadIdx.x], shist[threadIdx.x]);
    if (threadIdx.x == 0) atomicAdd(&g_esti16, sesti);
}

// ---------------- mask_1 histogram (half res) ----------------
__global__ void k_mask1(const float* __restrict__ thresh,
                        const float* __restrict__ centers) {
    __shared__ float sc[8];
    __shared__ unsigned int shist[8];
    __shared__ float sth[2];
    if (threadIdx.x < 8) { sc[threadIdx.x] = centers[threadIdx.x]; shist[threadIdx.x] = 0u; }
    if (threadIdx.x < 2) sth[threadIdx.x] = thresh[threadIdx.x];
    __syncthreads();

    int i = blockIdx.x*blockDim.x + threadIdx.x;
    if (i < NB*NC*128*128) {
        int xp = i & 127, y = (i >> 7) & 127, bc = i >> 14;
        float f1 = 0.5f*(tanhf(g_h2[i]) + 1.0f);
        float f2 = 0.5f*(tanhf(g_h3[bc*4096 + (y >> 1)*64 + (xp >> 1)]) + 1.0f);
        if (f2 >= sth[1] && f1 < sth[0]) {
            float p = g_p1[i];
            float dmin = 3.4e38f; int imin = 0;
            #pragma unroll
            for (int k = 0; k < 8; k++) {
                float t = p - sc[k];
                float d = t*t;
                if (d < dmin) { dmin = d; imin = k; }
            }
            atomicAdd(&shist[imin], 1u);
        }
    }
    __syncthreads();
    if (threadIdx.x < 8 && shist[threadIdx.x]) atomicAdd(&g_counts[threadIdx.x], shist[threadIdx.x]);
}

// ---------------- mask_2 histogram (quarter res) ----------------
__global__ void k_mask2(const float* __restrict__ thresh,
                        const float* __restrict__ centers) {
    __shared__ float sc[8];
    __shared__ unsigned int shist[8];
    __shared__ float sth1;
    if (threadIdx.x < 8) { sc[threadIdx.x] = centers[threadIdx.x]; shist[threadIdx.x] = 0u; }
    if (threadIdx.x == 0) sth1 = thresh[1];
    __syncthreads();

    int i = blockIdx.x*blockDim.x + threadIdx.x;
    if (i < NB*NC*64*64) {
        float f2 = 0.5f*(tanhf(g_h3[i]) + 1.0f);
        if (f2 < sth1) {
            float p = g_p2[i];
            float dmin = 3.4e38f; int imin = 0;
            #pragma unroll
            for (int k = 0; k < 8; k++) {
                float t = p - sc[k];
                float d = t*t;
                if (d < dmin) { dmin = d; imin = k; }
            }
            atomicAdd(&shist[imin], 1u);
        }
    }
    __syncthreads();
    if (threadIdx.x < 8 && shist[threadIdx.x]) atomicAdd(&g_counts[threadIdx.x], shist[threadIdx.x]);
}

// ---------------- finalize scalars ----------------
__global__ void k_fin(float* __restrict__ out, int soft_n) {
    if (threadIdx.x == 0 && blockIdx.x == 0) {
        double tot = 0.0;
        for (int k = 0; k < 8; k++) tot += (double)g_counts[k];
        double c[8];
        double mean = 0.0;
        for (int k = 0; k < 8; k++) { c[k] = (double)g_counts[k] / tot; mean += c[k]; }
        mean /= 8.0;
        double var = 0.0;
        for (int k = 0; k < 8; k++) { double d = c[k] - mean; var += d*d; }
        double stdv = sqrt(var / 7.0);
        double esti = (double)g_esti16 / 16.0;
        double cr = (1.0/16.0) * esti / (256.0*256.0*3.0*8.0);
        out[soft_n]     = (float)cr;
        out[soft_n + 1] = (float)stdv;
    }
}

// ---------------- launch ----------------
extern "C" void kernel_launch(void* const* d_in, const int* in_sizes, int n_in,
                              void* d_out, int out_size) {
    const float* x_init   = (const float*)d_in[0];
    const float* thresh   = (const float*)d_in[1];
    const float* sample_w = (const float*)d_in[2];
    const float* sample_b = (const float*)d_in[3];
    const float* centers  = (const float*)d_in[4];
    const float* pool1_w  = (const float*)d_in[5];
    const float* pool1_b  = (const float*)d_in[6];
    const float* pool2_w  = (const float*)d_in[7];
    const float* pool2_b  = (const float*)d_in[8];
    const float* ctx_w    = (const float*)d_in[9];
    const float* ctx_b    = (const float*)d_in[10];
    const float* bng      = (const float*)d_in[11];
    const float* bnb      = (const float*)d_in[12];
    float* out = (float*)d_out;
    int soft_n = out_size - 2;

    k_init<<<1, 32>>>(sample_w);
    k_sample<<<dim3(256, 8), 256>>>(x_init, sample_w, sample_b);
    k_ctx<0><<<dim3(512, 8), 512>>>(x_init, ctx_w + 0*81, ctx_b + 0*3, bng + 0*3, bnb + 0*3);
    k_ctx<1><<<dim3(256, 8), 256>>>(x_init, ctx_w + 1*81, ctx_b + 1*3, bng + 1*3, bnb + 1*3);
    k_ctx<2><<<dim3(128, 8), 128>>>(x_init, ctx_w + 2*81, ctx_b + 2*3, bng + 2*3, bnb + 2*3);
    k_ctx<3><<<dim3(64, 8),  64>>> (x_init, ctx_w + 3*81, ctx_b + 3*3, bng + 3*3, bnb + 3*3);
    k_pool<0><<<dim3(128, 8), 128>>>(pool1_w, pool1_b);
    k_pool<1><<<dim3(64, 8),  64>>> (pool2_w, pool2_b);
    k_main<<<(NB*NC*256*256 + 255)/256, 256>>>(thresh, centers, out);
    k_mask1<<<(NB*NC*128*128 + 255)/256, 256>>>(thresh, centers);
    k_mask2<<<(NB*NC*64*64 + 255)/256, 256>>>(thresh, centers);
    k_fin<<<1, 32>>>(out, soft_n);
}

// round 2
// speedup vs baseline: 3.9261x; 3.9261x over previous
#include <cuda_runtime.h>
#include <math.h>

#define NB 8
#define NC 3

// ---------------- scratch (device globals; no runtime allocation) ----------------
__device__ float g_x [NB*NC*256*256];   // sample conv output
__device__ float g_h0[NB*NC*512*512];   // ctx stage 0 out
__device__ float g_h1[NB*NC*256*256];   // ctx stage 1 out
__device__ float g_h2[NB*NC*128*128];   // ctx stage 2 out (pre-tanh feat_1)
__device__ float g_h3[NB*NC*64*64];     // ctx stage 3 out (pre-tanh feat_2)
__device__ float g_p1[NB*NC*128*128];
__device__ float g_p2[NB*NC*64*64];
__device__ float g_inv_sigma;
__device__ unsigned int g_counts[8];
__device__ unsigned int g_esti16;       // esti_size in units of 1/16 (exact integer)

// ---------------- init: zero accumulators + spectral norm of sample_w ----------------
// Largest singular value of the (3,48) matrix == sqrt(largest eigenvalue of the
// 3x3 symmetric Gram G = A A^T). Use the closed-form trigonometric eigenvalue
// formula instead of serial power iteration (which cost ~350us on one thread).
__global__ void k_init(const float* __restrict__ w) {
    __shared__ double sG[9];
    int t = threadIdx.x;
    if (t < 8) g_counts[t] = 0u;
    if (t == 0) g_esti16 = 0u;
    if (t < 9) {
        int i = t / 3, j = t % 3;
        // 4-way unrolled dot product to break the DFMA dependency chain
        double s0 = 0.0, s1 = 0.0, s2 = 0.0, s3 = 0.0;
        #pragma unroll
        for (int k = 0; k < 48; k += 4) {
            s0 += (double)w[i*48 + k + 0] * (double)w[j*48 + k + 0];
            s1 += (double)w[i*48 + k + 1] * (double)w[j*48 + k + 1];
            s2 += (double)w[i*48 + k + 2] * (double)w[j*48 + k + 2];
            s3 += (double)w[i*48 + k + 3] * (double)w[j*48 + k + 3];
        }
        sG[t] = (s0 + s1) + (s2 + s3);
    }
    __syncthreads();
    if (t == 0) {
        double g00 = sG[0], g01 = sG[1], g02 = sG[2];
        double g11 = sG[4], g12 = sG[5], g22 = sG[8];
        double q  = (g00 + g11 + g22) / 3.0;
        double p1 = g01*g01 + g02*g02 + g12*g12;
        double d0 = g00 - q, d1 = g11 - q, d2 = g22 - q;
        double p2 = d0*d0 + d1*d1 + d2*d2 + 2.0*p1;
        double lam;
        if (p2 <= 1e-300) {
            lam = q;   // G is (numerically) q*I
        } else {
            double p = sqrt(p2 / 6.0);
            double ip = 1.0 / p;
            double b00 = d0*ip, b11 = d1*ip, b22 = d2*ip;
            double b01 = g01*ip, b02 = g02*ip, b12 = g12*ip;
            double detB = b00*(b11*b22 - b12*b12)
                        - b01*(b01*b22 - b12*b02)
                        + b02*(b01*b12 - b11*b02);
            double r = 0.5 * detB;
            r = fmin(1.0, fmax(-1.0, r));
            double phi = acos(r) / 3.0;
            lam = q + 2.0*p*cos(phi);
        }
        g_inv_sigma = (float)(1.0 / sqrt(lam));
    }
}

// ---------------- sample conv: 4x4, stride 4, pad 0; 1024 -> 256 ----------------
__global__ void k_sample(const float* __restrict__ x,
                         const float* __restrict__ w,
                         const float* __restrict__ bias) {
    __shared__ float sw[144];
    __shared__ float sb[3];
    __shared__ float sinv;
    for (int j = threadIdx.x; j < 144; j += 256) sw[j] = w[j];
    if (threadIdx.x < 3) sb[threadIdx.x] = bias[threadIdx.x];
    if (threadIdx.x == 0) sinv = g_inv_sigma;
    __syncthreads();

    int ox = threadIdx.x;      // 0..255
    int oy = blockIdx.x;       // 0..255
    int b  = blockIdx.y;       // 0..7
    float a0 = 0.f, a1 = 0.f, a2 = 0.f;
    #pragma unroll
    for (int ic = 0; ic < 3; ic++) {
        const float* base = x + (((b*3 + ic)*1024) + oy*4)*1024 + ox*4;
        #pragma unroll
        for (int ky = 0; ky < 4; ky++) {
            float4 v = *reinterpret_cast<const float4*>(base + ky*1024);
            const float* w0 = &sw[((0*3 + ic)*4 + ky)*4];
            const float* w1 = &sw[((1*3 + ic)*4 + ky)*4];
            const float* w2 = &sw[((2*3 + ic)*4 + ky)*4];
            a0 += w0[0]*v.x + w0[1]*v.y + w0[2]*v.z + w0[3]*v.w;
            a1 += w1[0]*v.x + w1[1]*v.y + w1[2]*v.z + w1[3]*v.w;
            a2 += w2[0]*v.x + w2[1]*v.y + w2[2]*v.z + w2[3]*v.w;
        }
    }
    g_x[((b*3 + 0)*256 + oy)*256 + ox] = a0*sinv + sb[0];
    g_x[((b*3 + 1)*256 + oy)*256 + ox] = a1*sinv + sb[1];
    g_x[((b*3 + 2)*256 + oy)*256 + ox] = a2*sinv + sb[2];
}

// ---------------- ctx conv stage: conv3x3(s2,p1) of relu(bn(in)) ----------------
template<int STAGE>
__global__ void k_ctx(const float* __restrict__ xin,
                      const float* __restrict__ w,
                      const float* __restrict__ bias,
                      const float* __restrict__ bng,
                      const float* __restrict__ bnb) {
    const float* in;
    float* out;
    int inH;
    if (STAGE == 0)      { in = xin;  out = g_h0; inH = 1024; }
    else if (STAGE == 1) { in = g_h0; out = g_h1; inH = 512; }
    else if (STAGE == 2) { in = g_h1; out = g_h2; inH = 256; }
    else                 { in = g_h2; out = g_h3; inH = 128; }
    const int inW = inH, outH = inH >> 1, outW = inW >> 1;

    __shared__ float sw[81];
    __shared__ float sb[3], sinv[3], sbb[3];
    for (int j = threadIdx.x; j < 81; j += blockDim.x) sw[j] = w[j];
    if (threadIdx.x < 3) {
        sb[threadIdx.x]  = bias[threadIdx.x];
        sinv[threadIdx.x] = bng[threadIdx.x] / sqrtf(1.001f);
        sbb[threadIdx.x] = bnb[threadIdx.x];
    }
    __syncthreads();

    int ox = threadIdx.x;
    if (ox >= outW) return;
    int oy = blockIdx.x;
    int b  = blockIdx.y;

    float a0 = sb[0], a1 = sb[1], a2 = sb[2];
    #pragma unroll
    for (int ic = 0; ic < 3; ic++) {
        const float* base = in + (size_t)(b*3 + ic)*inH*inW;
        float inv = sinv[ic], bb = sbb[ic];
        #pragma unroll
        for (int ky = 0; ky < 3; ky++) {
            int iy = 2*oy + ky - 1;
            if ((unsigned)iy >= (unsigned)inH) continue;
            #pragma unroll
            for (int kx = 0; kx < 3; kx++) {
                int ix = 2*ox + kx - 1;
                if ((unsigned)ix >= (unsigned)inW) continue;
                float v = base[iy*inW + ix];
                v = fmaxf(fmaf(inv, v, bb), 0.0f);     // relu(bn(.)) then zero-pad
                int wi = ic*9 + ky*3 + kx;
                a0 = fmaf(sw[wi],      v, a0);
                a1 = fmaf(sw[27 + wi], v, a1);
                a2 = fmaf(sw[54 + wi], v, a2);
            }
        }
    }
    out[((b*3 + 0)*outH + oy)*outW + ox] = a0;
    out[((b*3 + 1)*outH + oy)*outW + ox] = a1;
    out[((b*3 + 2)*outH + oy)*outW + ox] = a2;
}

// ---------------- pool conv: 2x2 stride 2 pad 0 ----------------
template<int STAGE>
__global__ void k_pool(const float* __restrict__ w,
                       const float* __restrict__ bias) {
    const float* in;
    float* out;
    int inH;
    if (STAGE == 0) { in = g_x;  out = g_p1; inH = 256; }
    else            { in = g_p1; out = g_p2; inH = 128; }
    const int inW = inH, outH = inH >> 1, outW = inW >> 1;

    __shared__ float sw[36];
    __shared__ float sb[3];
    for (int j = threadIdx.x; j < 36; j += blockDim.x) sw[j] = w[j];
    if (threadIdx.x < 3) sb[threadIdx.x] = bias[threadIdx.x];
    __syncthreads();

    int ox = threadIdx.x;
    if (ox >= outW) return;
    int oy = blockIdx.x;
    int b  = blockIdx.y;

    float a0 = sb[0], a1 = sb[1], a2 = sb[2];
    #pragma unroll
    for (int ic = 0; ic < 3; ic++) {
        const float* base = in + ((size_t)(b*3 + ic)*inH + 2*oy)*inW + 2*ox;
        float2 r0 = *reinterpret_cast<const float2*>(base);
        float2 r1 = *reinterpret_cast<const float2*>(base + inW);
        const float* w0 = &sw[(0*3 + ic)*4];
        const float* w1 = &sw[(1*3 + ic)*4];
        const float* w2 = &sw[(2*3 + ic)*4];
        a0 += w0[0]*r0.x + w0[1]*r0.y + w0[2]*r1.x + w0[3]*r1.y;
        a1 += w1[0]*r0.x + w1[1]*r0.y + w1[2]*r1.x + w1[3]*r1.y;
        a2 += w2[0]*r0.x + w2[1]*r0.y + w2[2]*r1.x + w2[3]*r1.y;
    }
    out[((b*3 + 0)*outH + oy)*outW + ox] = a0;
    out[((b*3 + 1)*outH + oy)*outW + ox] = a1;
    out[((b*3 + 2)*outH + oy)*outW + ox] = a2;
}

// ---------------- main fused pass: conditions + soft VQ + stats ----------------
__global__ void k_main(const float* __restrict__ thresh,
                       const float* __restrict__ centers,
                       float* __restrict__ out) {
    __shared__ float sc[8];
    __shared__ unsigned int shist[8];
    __shared__ unsigned int sesti;
    __shared__ float sth[2];
    if (threadIdx.x < 8) { sc[threadIdx.x] = centers[threadIdx.x]; shist[threadIdx.x] = 0u; }
    if (threadIdx.x < 2) sth[threadIdx.x] = thresh[threadIdx.x];
    if (threadIdx.x == 0) sesti = 0u;
    __syncthreads();

    int i = blockIdx.x*blockDim.x + threadIdx.x;
    unsigned int ev = 0u;
    if (i < NB*NC*256*256) {
        int xp = i & 255, y = (i >> 8) & 255, bc = i >> 16;
        float xv = g_x[i];
        int hi = bc*16384 + (y >> 1)*128 + (xp >> 1);  // half-res index
        int qi = bc*4096  + (y >> 2)*64  + (xp >> 2);  // quarter-res index
        float f1 = 0.5f*(tanhf(g_h2[hi]) + 1.0f);
        float f2 = 0.5f*(tanhf(g_h3[qi]) + 1.0f);
        bool c2 = f2 < sth[1];
        bool c1 = (!c2) && (f1 < sth[0]);
        bool c0 = !(c1 || c2);
        float xq = xv;
        if (c1) xq = g_p1[hi];
        if (c2) xq = g_p2[qi];

        float dd[8];
        float dmin = 3.4e38f;
        int imin = 0;
        #pragma unroll
        for (int k = 0; k < 8; k++) {
            float t = xq - sc[k];
            dd[k] = t*t;
            if (dd[k] < dmin) { dmin = dd[k]; imin = k; }
        }
        float s = 0.f, sn = 0.f;
        #pragma unroll
        for (int k = 0; k < 8; k++) {
            float e = __expf(dmin - dd[k]);
            s += e;
            sn = fmaf(e, sc[k], sn);
        }
        out[i] = sn / s;

        ev = c0 ? 16u : (c1 ? 4u : 1u);
        // cond_0 => xq == xv, so imin is argmin over x's distances too
        if (c0) atomicAdd(&shist[imin], 1u);
    }
    unsigned int wsum = __reduce_add_sync(0xffffffffu, ev);
    if ((threadIdx.x & 31) == 0) atomicAdd(&sesti, wsum);
    __syncthreads();
    if (threadIdx.x < 8 && shist[threadIdx.x]) atomicAdd(&g_counts[threadIdx.x], shist[threadIdx.x]);
    if (threadIdx.x == 0) atomicAdd(&g_esti16, sesti);
}

// ---------------- mask_1 histogram (half res) ----------------
__global__ void k_mask1(const float* __restrict__ thresh,
                        const float* __restrict__ centers) {
    __shared__ float sc[8];
    __shared__ unsigned int shist[8];
    __shared__ float sth[2];
    if (threadIdx.x < 8) { sc[threadIdx.x] = centers[threadIdx.x]; shist[threadIdx.x] = 0u; }
    if (threadIdx.x < 2) sth[threadIdx.x] = thresh[threadIdx.x];
    __syncthreads();

    int i = blockIdx.x*blockDim.x + threadIdx.x;
    if (i < NB*NC*128*128) {
        int xp = i & 127, y = (i >> 7) & 127, bc = i >> 14;
        float f1 = 0.5f*(tanhf(g_h2[i]) + 1.0f);
        float f2 = 0.5f*(tanhf(g_h3[bc*4096 + (y >> 1)*64 + (xp >> 1)]) + 1.0f);
        if (f2 >= sth[1] && f1 < sth[0]) {
            float p = g_p1[i];
            float dmin = 3.4e38f; int imin = 0;
            #pragma unroll
            for (int k = 0; k < 8; k++) {
                float t = p - sc[k];
                float d = t*t;
                if (d < dmin) { dmin = d; imin = k; }
            }
            atomicAdd(&shist[imin], 1u);
        }
    }
    __syncthreads();
    if (threadIdx.x < 8 && shist[threadIdx.x]) atomicAdd(&g_counts[threadIdx.x], shist[threadIdx.x]);
}

// ---------------- mask_2 histogram (quarter res) ----------------
__global__ void k_mask2(const float* __restrict__ thresh,
                        const float* __restrict__ centers) {
    __shared__ float sc[8];
    __shared__ unsigned int shist[8];
    __shared__ float sth1;
    if (threadIdx.x < 8) { sc[threadIdx.x] = centers[threadIdx.x]; shist[threadIdx.x] = 0u; }
    if (threadIdx.x == 0) sth1 = thresh[1];
    __syncthreads();

    int i = blockIdx.x*blockDim.x + threadIdx.x;
    if (i < NB*NC*64*64) {
        float f2 = 0.5f*(tanhf(g_h3[i]) + 1.0f);
        if (f2 < sth1) {
            float p = g_p2[i];
            float dmin = 3.4e38f; int imin = 0;
            #pragma unroll
            for (int k = 0; k < 8; k++) {
                float t = p - sc[k];
                float d = t*t;
                if (d < dmin) { dmin = d; imin = k; }
            }
            atomicAdd(&shist[imin], 1u);
        }
    }
    __syncthreads();
    if (threadIdx.x < 8 && shist[threadIdx.x]) atomicAdd(&g_counts[threadIdx.x], shist[threadIdx.x]);
}

// ---------------- finalize scalars ----------------
__global__ void k_fin(float* __restrict__ out, int soft_n) {
    if (threadIdx.x == 0 && blockIdx.x == 0) {
        double tot = 0.0;
        for (int k = 0; k < 8; k++) tot += (double)g_counts[k];
        double c[8];
        double mean = 0.0;
        for (int k = 0; k < 8; k++) { c[k] = (double)g_counts[k] / tot; mean += c[k]; }
        mean /= 8.0;
        double var = 0.0;
        for (int k = 0; k < 8; k++) { double d = c[k] - mean; var += d*d; }
        double stdv = sqrt(var / 7.0);
        double esti = (double)g_esti16 / 16.0;
        double cr = (1.0/16.0) * esti / (256.0*256.0*3.0*8.0);
        out[soft_n]     = (float)cr;
        out[soft_n + 1] = (float)stdv;
    }
}

// ---------------- launch ----------------
extern "C" void kernel_launch(void* const* d_in, const int* in_sizes, int n_in,
                              void* d_out, int out_size) {
    const float* x_init   = (const float*)d_in[0];
    const float* thresh   = (const float*)d_in[1];
    const float* sample_w = (const float*)d_in[2];
    const float* sample_b = (const float*)d_in[3];
    const float* centers  = (const float*)d_in[4];
    const float* pool1_w  = (const float*)d_in[5];
    const float* pool1_b  = (const float*)d_in[6];
    const float* pool2_w  = (const float*)d_in[7];
    const float* pool2_b  = (const float*)d_in[8];
    const float* ctx_w    = (const float*)d_in[9];
    const float* ctx_b    = (const float*)d_in[10];
    const float* bng      = (const float*)d_in[11];
    const float* bnb      = (const float*)d_in[12];
    float* out = (float*)d_out;
    int soft_n = out_size - 2;

    k_init<<<1, 32>>>(sample_w);
    k_sample<<<dim3(256, 8), 256>>>(x_init, sample_w, sample_b);
    k_ctx<0><<<dim3(512, 8), 512>>>(x_init, ctx_w + 0*81, ctx_b + 0*3, bng + 0*3, bnb + 0*3);
    k_ctx<1><<<dim3(256, 8), 256>>>(x_init, ctx_w + 1*81, ctx_b + 1*3, bng + 1*3, bnb + 1*3);
    k_ctx<2><<<dim3(128, 8), 128>>>(x_init, ctx_w + 2*81, ctx_b + 2*3, bng + 2*3, bnb + 2*3);
    k_ctx<3><<<dim3(64, 8),  64>>> (x_init, ctx_w + 3*81, ctx_b + 3*3, bng + 3*3, bnb + 3*3);
    k_pool<0><<<dim3(128, 8), 128>>>(pool1_w, pool1_b);
    k_pool<1><<<dim3(64, 8),  64>>> (pool2_w, pool2_b);
    k_main<<<(NB*NC*256*256 + 255)/256, 256>>>(thresh, centers, out);
    k_mask1<<<(NB*NC*128*128 + 255)/256, 256>>>(thresh, centers);
    k_mask2<<<(NB*NC*64*64 + 255)/256, 256>>>(thresh, centers);
    k_fin<<<1, 32>>>(out, soft_n);
}